// round 14
// baseline (speedup 1.0000x reference)
#include <cuda_runtime.h>
#include <cuda_bf16.h>
#include <cstdint>
#include <math.h>

// dims
#define B_ 4096
#define D_ 256
#define H_ 1024
#define K_ 128
#define ND (B_*D_)
#define NV (ND/4)
#define NMAX 6
#define RTOL 1e-3f
#define ATOL 1e-3f

// dopri5 error coefficients (c_sol - c_bhat)
#define CE0 ((float)(35.0/384.0 - 1951.0/21600.0))
#define CE2 ((float)(500.0/1113.0 - 22642.0/50085.0))
#define CE3 ((float)(125.0/192.0 - 451.0/720.0))
#define CE4 ((float)(-2187.0/6784.0 + 12231.0/42400.0))
#define CE5 ((float)(11.0/84.0 - 649.0/6300.0))
#define CE6 ((float)(-1.0/60.0))
// dopri5 midpoint coefficients (interp fit)
#define CM0 ((float)(6025192743.0/30085553152.0/2.0))
#define CM2 ((float)(51252292925.0/65400821598.0/2.0))
#define CM3 ((float)(-2691868925.0/45128329728.0/2.0))
#define CM4 ((float)(187940372067.0/1594534317056.0/2.0))
#define CM5 ((float)(-1776094331.0/19743644256.0/2.0))
#define CM6 ((float)(11237099.0/235043384.0/2.0))

struct Ctl {
    float t, dt, last_t, dt_used, h0, d1;
    int accept, done;
};
__device__ Ctl g_ctl2[2];
__device__ __align__(16) float g_y[ND];
__device__ __align__(16) float g_y1[ND];
__device__ __align__(16) float g_k[7][ND];
__device__ __align__(16) float g_y0s[ND], g_ymid[ND], g_f0s[ND], g_f1s[ND];
__device__ __align__(16) float g_yout[ND];
__device__ __align__(16) float g_part[2048];
__device__ __align__(16) __nv_bfloat16 g_Xhi[ND], g_Xlo[ND];
__device__ __align__(16) __nv_bfloat16 g_Hhi[B_ * H_], g_Hlo[B_ * H_];
__device__ __align__(16) __nv_bfloat16 g_W1thi[H_ * D_], g_W1tlo[H_ * D_]; // W1^T [H,D]
__device__ __align__(16) __nv_bfloat16 g_W2thi[D_ * H_], g_W2tlo[D_ * H_]; // W2^T [D,H]

#define SWZ128(b) ((b) ^ (((b) >> 3) & 0x70))

__device__ __forceinline__ uint32_t smem_u32(const void* p) {
    uint32_t a;
    asm("{ .reg .u64 t; cvta.to.shared.u64 t, %1; cvt.u32.u64 %0, t; }" : "=r"(a) : "l"(p));
    return a;
}
__device__ __forceinline__ void cp16(uint32_t saddr, const void* gptr) {
    asm volatile("cp.async.cg.shared.global [%0], [%1], 16;" :: "r"(saddr), "l"(gptr));
}
#define CP_COMMIT() asm volatile("cp.async.commit_group;" ::: "memory")
#define CP_WAIT0()  asm volatile("cp.async.wait_group 0;" ::: "memory")
#define CP_WAIT1()  asm volatile("cp.async.wait_group 1;" ::: "memory")
__device__ __forceinline__ void ldsm_x4(uint32_t* r, uint32_t addr) {
    asm volatile("ldmatrix.sync.aligned.m8n8.x4.shared.b16 {%0,%1,%2,%3}, [%4];"
        : "=r"(r[0]), "=r"(r[1]), "=r"(r[2]), "=r"(r[3]) : "r"(addr));
}
__device__ __forceinline__ void mma16816(float* c, const uint32_t* a, const uint32_t* b) {
    asm volatile("mma.sync.aligned.m16n8k16.row.col.f32.bf16.bf16.f32 "
        "{%0,%1,%2,%3}, {%4,%5,%6,%7}, {%8,%9}, {%0,%1,%2,%3};"
        : "+f"(c[0]), "+f"(c[1]), "+f"(c[2]), "+f"(c[3])
        : "r"(a[0]), "r"(a[1]), "r"(a[2]), "r"(a[3]), "r"(b[0]), "r"(b[1]));
}
__device__ __forceinline__ void bf16_split2(float a, float b, __nv_bfloat162& h, __nv_bfloat162& l) {
    h.x = __float2bfloat16(a); h.y = __float2bfloat16(b);
    l.x = __float2bfloat16(a - __bfloat162float(h.x));
    l.y = __float2bfloat16(b - __bfloat162float(h.y));
}

// ================= small kernels =================
// weight prep W1 + ctl init
__global__ void prep_w1_kernel(const float* __restrict__ W1) {
    if (blockIdx.x == 0 && threadIdx.x == 0) {
        for (int j = 0; j < 2; j++) {
            g_ctl2[j].t = 0.f; g_ctl2[j].dt = 0.f; g_ctl2[j].last_t = 0.f;
            g_ctl2[j].dt_used = 0.f; g_ctl2[j].h0 = 0.f; g_ctl2[j].d1 = 0.f;
            g_ctl2[j].accept = 0; g_ctl2[j].done = 0;
        }
    }
    int o = blockIdx.x * 256 + threadIdx.x;
    if (o < H_ * D_) {
        int h = o >> 8, d = o & 255;
        float v = W1[(size_t)d * H_ + h];
        __nv_bfloat16 hi = __float2bfloat16(v);
        g_W1thi[o] = hi;
        g_W1tlo[o] = __float2bfloat16(v - __bfloat162float(hi));
    }
}
// W2 [H,D] -> W2t hi/lo [D,H]
__global__ void prep_w2_kernel(const float* __restrict__ W2) {
    int o = blockIdx.x * 256 + threadIdx.x;
    if (o < D_ * H_) {
        int d = o >> 10, h = o & 1023;
        float v = W2[(size_t)h * D_ + d];
        __nv_bfloat16 hi = __float2bfloat16(v);
        g_W2thi[o] = hi;
        g_W2tlo[o] = __float2bfloat16(v - __bfloat162float(hi));
    }
}

// y = x; X = x (bf16 split)
__global__ void copysplit_kernel(const float4* __restrict__ x) {
    int i = blockIdx.x * 256 + threadIdx.x;
    float4 X = x[i];
    ((float4*)g_y)[i] = X;
    __nv_bfloat162 h01, h23, l01, l23;
    bf16_split2(X.x, X.y, h01, l01);
    bf16_split2(X.z, X.w, h23, l23);
    ((__nv_bfloat162*)g_Xhi)[2*i]   = h01;
    ((__nv_bfloat162*)g_Xhi)[2*i+1] = h23;
    ((__nv_bfloat162*)g_Xlo)[2*i]   = l01;
    ((__nv_bfloat162*)g_Xlo)[2*i+1] = l23;
}

// init-phase combine + split: X = y + (*scal)*c0*k0
__global__ void split_combine_kernel(const float* __restrict__ scal, float c0)
{
    int i = blockIdx.x * 256 + threadIdx.x;
    float dt = *scal;
    float4 kv = ((const float4*)g_k[0])[i];
    float4 yv = ((const float4*)g_y)[i];
    float4 X = make_float4(yv.x + dt * c0 * kv.x, yv.y + dt * c0 * kv.y,
                           yv.z + dt * c0 * kv.z, yv.w + dt * c0 * kv.w);
    __nv_bfloat162 h01, h23, l01, l23;
    bf16_split2(X.x, X.y, h01, l01);
    bf16_split2(X.z, X.w, h23, l23);
    ((__nv_bfloat162*)g_Xhi)[2*i]   = h01;
    ((__nv_bfloat162*)g_Xhi)[2*i+1] = h23;
    ((__nv_bfloat162*)g_Xlo)[2*i]   = l01;
    ((__nv_bfloat162*)g_Xlo)[2*i+1] = l23;
}

// ================= GEMM1: H = tanh(X @ W1 + b1) =================
// tile 64x128, K=256 (4 chunks of 64), 512 threads (16 warps 4m x 4n, warp 16x32),
// 3-stage cp.async single-sync mainloop. grid (8, 64) = 512 CTAs.
#define G1_STAGE 49152
#define G1_SMEM  (3 * G1_STAGE)

__global__ void __launch_bounds__(512, 1) gemm1_kernel(int p, const float* __restrict__ bias)
{
    if (g_ctl2[p].done) return;
    extern __shared__ char smem[];
    const uint32_t smb = smem_u32(smem);

    const int tid = threadIdx.x;
    const int w = tid >> 5, l = tid & 31;
    const int wm = w >> 2, wn = w & 3;
    const int m0 = blockIdx.y * 64;
    const int n0 = blockIdx.x * 128;

    float acc[4][4];
#pragma unroll
    for (int nf = 0; nf < 4; nf++)
#pragma unroll
        for (int e = 0; e < 4; e++) acc[nf][e] = 0.f;

    const int rowA = wm * 16 + (l & 15);
    const int colA = (l >> 4) * 8;
    const int rowB4 = wn * 32 + ((l >> 4) * 8) + (l & 7);
    const int colB4 = ((l >> 3) & 1) * 8;

    auto load_chunk = [&](int c, int b) {
        const uint32_t base = smb + b * G1_STAGE;
        const int kc = c * 64;
        {   // A: 64 rows x 8 groups = 512 -> 1 iter
            int r = tid >> 3, g = tid & 7;
            size_t src = (size_t)(m0 + r) * D_ + kc + g * 8;
            uint32_t sw = SWZ128(r * 128 + g * 16);
            cp16(base + sw,         g_Xhi + src);
            cp16(base + 8192 + sw,  g_Xlo + src);
        }
#pragma unroll
        for (int i = 0; i < 2; i++) {  // B: 128 rows x 8 groups = 1024
            int t = tid + i * 512;
            int r = t >> 3, g = t & 7;
            size_t src = (size_t)(n0 + r) * D_ + kc + g * 8;
            uint32_t sw = SWZ128(r * 128 + g * 16);
            cp16(base + 16384 + sw, g_W1thi + src);
            cp16(base + 32768 + sw, g_W1tlo + src);
        }
    };

    load_chunk(0, 0); CP_COMMIT();
    load_chunk(1, 1); CP_COMMIT();

    for (int c = 0; c < 4; c++) {
        if (c < 3) CP_WAIT1(); else CP_WAIT0();
        __syncthreads();
        if (c + 2 < 4) { load_chunk(c + 2, (c + 2) % 3); CP_COMMIT(); }

        const uint32_t base = smb + (c % 3) * G1_STAGE;
        const uint32_t sAh = base, sAl = base + 8192;
        const uint32_t sBh = base + 16384, sBl = base + 32768;
#pragma unroll
        for (int kf = 0; kf < 4; kf++) {
            uint32_t ah[4], al[4], bh4[2][4], bl4[2][4];
            {
                uint32_t off = SWZ128(rowA * 128 + (kf * 16 + colA) * 2);
                ldsm_x4(ah, sAh + off);
                ldsm_x4(al, sAl + off);
            }
#pragma unroll
            for (int pb = 0; pb < 2; pb++) {
                uint32_t off = SWZ128((rowB4 + pb * 16) * 128 + (kf * 16 + colB4) * 2);
                ldsm_x4(bh4[pb], sBh + off);
                ldsm_x4(bl4[pb], sBl + off);
            }
#pragma unroll
            for (int nf = 0; nf < 4; nf++) {
                const uint32_t* bhf = &bh4[nf >> 1][(nf & 1) * 2];
                const uint32_t* blf = &bl4[nf >> 1][(nf & 1) * 2];
                mma16816(acc[nf], ah, bhf);
                mma16816(acc[nf], ah, blf);
                mma16816(acc[nf], al, bhf);
            }
        }
    }

    const int rr = l >> 2;
    const int cc2 = (l & 3) * 2;
#pragma unroll
    for (int nf = 0; nf < 4; nf++) {
        int r0 = m0 + wm * 16 + rr;
        int ci = n0 + wn * 32 + nf * 8 + cc2;
        float2 bb = *(const float2*)&bias[ci];
#pragma unroll
        for (int hh = 0; hh < 2; hh++) {
            int r = r0 + hh * 8;
            float v0 = tanhf(acc[nf][hh * 2 + 0] + bb.x);
            float v1 = tanhf(acc[nf][hh * 2 + 1] + bb.y);
            __nv_bfloat162 h, lo2;
            bf16_split2(v0, v1, h, lo2);
            *(__nv_bfloat162*)&g_Hhi[(size_t)r * H_ + ci] = h;
            *(__nv_bfloat162*)&g_Hlo[(size_t)r * H_ + ci] = lo2;
        }
    }
}

// ================= GEMM2: k = H @ W2 + b2, epilogue-fused =================
// tile 64x128, K=1024 (16 chunks), 512 threads (16 warps, 4m x 4n, warp 16x32),
// 3-stage cp.async single-sync mainloop. grid (2, 64) = 128 CTAs (1/SM).
#define G2_STAGE 49152
#define G2_SMEM  (3 * G2_STAGE)

__global__ void __launch_bounds__(512, 1) gemm2_kernel(
    int p, const float* __restrict__ b2, float* __restrict__ kout,
    int mode, int ngm,
    float cg0, float cg1, float cg2, float cg3, float cg4, float cg5, float cl)
{
    const Ctl& ct = g_ctl2[p];
    if (ct.done) return;
    extern __shared__ char smem[];
    const uint32_t smb = smem_u32(smem);

    const int tid = threadIdx.x;
    const int w = tid >> 5, l = tid & 31;
    const int wm = w >> 2, wn = w & 3;
    const int m0 = blockIdx.y * 64;
    const int n0 = blockIdx.x * 128;
    float cg[6] = {cg0, cg1, cg2, cg3, cg4, cg5};

    float acc[4][4];
#pragma unroll
    for (int nf = 0; nf < 4; nf++)
#pragma unroll
        for (int e = 0; e < 4; e++) acc[nf][e] = 0.f;

    const int rowA = wm * 16 + (l & 15);
    const int colA = (l >> 4) * 8;
    const int rowB4 = wn * 32 + ((l >> 4) * 8) + (l & 7);
    const int colB4 = ((l >> 3) & 1) * 8;

    auto load_chunk = [&](int c, int b) {
        const uint32_t base = smb + b * G2_STAGE;
        const int kc = c * 64;
        {
            int r = tid >> 3, g = tid & 7;
            size_t src = (size_t)(m0 + r) * H_ + kc + g * 8;
            uint32_t sw = SWZ128(r * 128 + g * 16);
            cp16(base + sw,         g_Hhi + src);
            cp16(base + 8192 + sw,  g_Hlo + src);
        }
#pragma unroll
        for (int i = 0; i < 2; i++) {
            int t = tid + i * 512;
            int r = t >> 3, g = t & 7;
            size_t src = (size_t)(n0 + r) * H_ + kc + g * 8;
            uint32_t sw = SWZ128(r * 128 + g * 16);
            cp16(base + 16384 + sw, g_W2thi + src);
            cp16(base + 32768 + sw, g_W2tlo + src);
        }
    };

    load_chunk(0, 0); CP_COMMIT();
    load_chunk(1, 1); CP_COMMIT();

    for (int c = 0; c < 16; c++) {
        if (c < 15) CP_WAIT1(); else CP_WAIT0();
        __syncthreads();
        if (c + 2 < 16) { load_chunk(c + 2, (c + 2) % 3); CP_COMMIT(); }

        const uint32_t base = smb + (c % 3) * G2_STAGE;
        const uint32_t sAh = base, sAl = base + 8192;
        const uint32_t sBh = base + 16384, sBl = base + 32768;
#pragma unroll
        for (int kf = 0; kf < 4; kf++) {
            uint32_t ah[4], al[4], bh4[2][4], bl4[2][4];
            {
                uint32_t off = SWZ128(rowA * 128 + (kf * 16 + colA) * 2);
                ldsm_x4(ah, sAh + off);
                ldsm_x4(al, sAl + off);
            }
#pragma unroll
            for (int pb = 0; pb < 2; pb++) {
                uint32_t off = SWZ128((rowB4 + pb * 16) * 128 + (kf * 16 + colB4) * 2);
                ldsm_x4(bh4[pb], sBh + off);
                ldsm_x4(bl4[pb], sBl + off);
            }
#pragma unroll
            for (int nf = 0; nf < 4; nf++) {
                const uint32_t* bhf = &bh4[nf >> 1][(nf & 1) * 2];
                const uint32_t* blf = &bl4[nf >> 1][(nf & 1) * 2];
                mma16816(acc[nf], ah, bhf);
                mma16816(acc[nf], ah, blf);
                mma16816(acc[nf], al, bhf);
            }
        }
    }

    // epilogue
    const int rr = l >> 2;
    const int cc2 = (l & 3) * 2;
    const float dt = ct.dt;
    float errsum = 0.f;
#pragma unroll
    for (int nf = 0; nf < 4; nf++) {
        int r0 = m0 + wm * 16 + rr;
        int ci = n0 + wn * 32 + nf * 8 + cc2;
        float2 bb = *(const float2*)&b2[ci];
#pragma unroll
        for (int hh = 0; hh < 2; hh++) {
            int r = r0 + hh * 8;
            float v0 = acc[nf][hh * 2 + 0] + bb.x;
            float v1 = acc[nf][hh * 2 + 1] + bb.y;
            size_t off = (size_t)r * D_ + ci;
            *(float2*)&kout[off] = make_float2(v0, v1);
            if (mode == 1 || mode == 3) {
                float2 yv = *(const float2*)&g_y[off];
                float sx = cl * v0, sy = cl * v1;
                for (int j = 0; j < ngm; j++) {
                    if (cg[j] != 0.f) {
                        float2 kj = *(const float2*)&g_k[j][off];
                        sx += cg[j] * kj.x; sy += cg[j] * kj.y;
                    }
                }
                float X0 = yv.x + dt * sx, X1 = yv.y + dt * sy;
                if (mode == 3) *(float2*)&g_y1[off] = make_float2(X0, X1);
                __nv_bfloat162 h, lo2;
                bf16_split2(X0, X1, h, lo2);
                *(__nv_bfloat162*)&g_Xhi[off] = h;
                *(__nv_bfloat162*)&g_Xlo[off] = lo2;
            } else if (mode == 2) {
                float2 yv  = *(const float2*)&g_y[off];
                float2 y1v = *(const float2*)&g_y1[off];
                float sx = cl * v0, sy = cl * v1;
                for (int j = 0; j < ngm; j++) {
                    if (cg[j] != 0.f) {
                        float2 kj = *(const float2*)&g_k[j][off];
                        sx += cg[j] * kj.x; sy += cg[j] * kj.y;
                    }
                }
                float e0 = dt * sx, e1 = dt * sy;
                float t0 = ATOL + RTOL * fmaxf(fabsf(yv.x), fabsf(y1v.x));
                float t1 = ATOL + RTOL * fmaxf(fabsf(yv.y), fabsf(y1v.y));
                float r0f = e0 / t0, r1f = e1 / t1;
                errsum += r0f * r0f + r1f * r1f;
            }
        }
    }
    if (mode == 2) {
        float* sred = (float*)smem;
        __syncthreads();
        sred[tid] = errsum;
        __syncthreads();
        for (int o = 256; o > 0; o >>= 1) {
            if (tid < o) sred[tid] += sred[tid + o];
            __syncthreads();
        }
        if (tid == 0) g_part[blockIdx.y * gridDim.x + blockIdx.x] = sred[0];
    }
}

// ---------------- init-step-size reductions (ctl2[0]) ----------------
__global__ void red_d01_kernel() {
    int i = blockIdx.x * 256 + threadIdx.x;
    float4 yv = ((const float4*)g_y)[i];
    float4 fv = ((const float4*)g_k[0])[i];
    float s0 = 0.f, s1 = 0.f;
    {
        float sc, a, b;
        sc = ATOL + fabsf(yv.x) * RTOL; a = yv.x / sc; b = fv.x / sc; s0 += a*a; s1 += b*b;
        sc = ATOL + fabsf(yv.y) * RTOL; a = yv.y / sc; b = fv.y / sc; s0 += a*a; s1 += b*b;
        sc = ATOL + fabsf(yv.z) * RTOL; a = yv.z / sc; b = fv.z / sc; s0 += a*a; s1 += b*b;
        sc = ATOL + fabsf(yv.w) * RTOL; a = yv.w / sc; b = fv.w / sc; s0 += a*a; s1 += b*b;
    }
    __shared__ float sm0[256], sm1[256];
    sm0[threadIdx.x] = s0; sm1[threadIdx.x] = s1;
    __syncthreads();
    for (int off = 128; off > 0; off >>= 1) {
        if (threadIdx.x < off) {
            sm0[threadIdx.x] += sm0[threadIdx.x + off];
            sm1[threadIdx.x] += sm1[threadIdx.x + off];
        }
        __syncthreads();
    }
    if (threadIdx.x == 0) { g_part[blockIdx.x] = sm0[0]; g_part[1024 + blockIdx.x] = sm1[0]; }
}

__global__ void fin_d01_kernel() {
    __shared__ float sm0[256], sm1[256];
    float s0 = 0.f, s1 = 0.f;
    for (int j = threadIdx.x; j < 1024; j += 256) { s0 += g_part[j]; s1 += g_part[1024 + j]; }
    sm0[threadIdx.x] = s0; sm1[threadIdx.x] = s1;
    __syncthreads();
    for (int off = 128; off > 0; off >>= 1) {
        if (threadIdx.x < off) {
            sm0[threadIdx.x] += sm0[threadIdx.x + off];
            sm1[threadIdx.x] += sm1[threadIdx.x + off];
        }
        __syncthreads();
    }
    if (threadIdx.x == 0) {
        float d0 = sqrtf(sm0[0]);
        float d1 = sqrtf(sm1[0]);
        float h0 = (d0 < 1e-5f || d1 < 1e-5f) ? 1e-6f : 0.01f * d0 / d1;
        g_ctl2[0].h0 = h0;
        g_ctl2[0].d1 = d1;
    }
}

__global__ void red_d2_kernel() {
    int i = blockIdx.x * 256 + threadIdx.x;
    float4 yv = ((const float4*)g_y)[i];
    float4 f0 = ((const float4*)g_k[0])[i];
    float4 f1 = ((const float4*)g_k[1])[i];
    float s = 0.f;
    {
        float sc, a;
        sc = ATOL + fabsf(yv.x) * RTOL; a = (f1.x - f0.x) / sc; s += a*a;
        sc = ATOL + fabsf(yv.y) * RTOL; a = (f1.y - f0.y) / sc; s += a*a;
        sc = ATOL + fabsf(yv.z) * RTOL; a = (f1.z - f0.z) / sc; s += a*a;
        sc = ATOL + fabsf(yv.w) * RTOL; a = (f1.w - f0.w) / sc; s += a*a;
    }
    __shared__ float sm[256];
    sm[threadIdx.x] = s;
    __syncthreads();
    for (int off = 128; off > 0; off >>= 1) {
        if (threadIdx.x < off) sm[threadIdx.x] += sm[threadIdx.x + off];
        __syncthreads();
    }
    if (threadIdx.x == 0) g_part[blockIdx.x] = sm[0];
}

__global__ void fin_d2_kernel() {
    __shared__ float sm[256];
    float s = 0.f;
    for (int j = threadIdx.x; j < 1024; j += 256) s += g_part[j];
    sm[threadIdx.x] = s;
    __syncthreads();
    for (int off = 128; off > 0; off >>= 1) {
        if (threadIdx.x < off) sm[threadIdx.x] += sm[threadIdx.x + off];
        __syncthreads();
    }
    if (threadIdx.x == 0) {
        float d2 = sqrtf(sm[0]) / g_ctl2[0].h0;
        float d1 = g_ctl2[0].d1;
        float h1;
        if (d1 <= 1e-15f && d2 <= 1e-15f)
            h1 = fmaxf(1e-6f, g_ctl2[0].h0 * 1e-3f);
        else
            h1 = powf(0.01f / fmaxf(d1, d2), 0.2f);
        float dt = fminf(100.f * g_ctl2[0].h0, h1);
        g_ctl2[0].dt = dt;
        g_ctl2[0].t = 0.f; g_ctl2[0].last_t = 0.f;
        g_ctl2[0].done = 0; g_ctl2[0].accept = 0;
    }
}

// ---------------- fused controller + apply + next-stage-1 combine ----------------
__global__ void applyctl_kernel(int p, float B21c) {
    const Ctl ci = g_ctl2[p];
    Ctl* co = &g_ctl2[1 - p];
    if (ci.done) {
        if (blockIdx.x == 0 && threadIdx.x == 0) *co = ci;
        return;
    }
    __shared__ float sm[128];
    if (threadIdx.x < 128) sm[threadIdx.x] = g_part[threadIdx.x];
    __syncthreads();
    for (int o = 64; o > 0; o >>= 1) {
        if (threadIdx.x < o) sm[threadIdx.x] += sm[threadIdx.x + o];
        __syncthreads();
    }
    float total = sm[0];

    float ratio = sqrtf(total / (float)ND);
    float t = ci.t, dt = ci.dt;
    float next_t = t + dt;
    int acc = (ratio <= 1.0f);
    float fac;
    if (ratio == 0.f) {
        fac = 10.f;
    } else {
        float r = fmaxf(ratio, 0.f);
        float dfac = (r < 1.f) ? 1.f : 0.2f;
        fac = fminf(10.f, fmaxf(0.9f * powf(r, -0.2f), dfac));
    }
    float ndt = fmaxf(dt * fac, 0.f);
    int done_new = (acc && next_t >= 1.0f) ? 1 : 0;

    if (blockIdx.x == 0 && threadIdx.x == 0) {
        co->t = acc ? next_t : t;
        co->dt = ndt;
        co->last_t = acc ? t : ci.last_t;
        co->dt_used = dt;
        co->h0 = ci.h0; co->d1 = ci.d1;
        co->accept = acc;
        co->done = done_new;
    }

    int i = blockIdx.x * 256 + threadIdx.x;
    float4 yv = ((const float4*)g_y)[i];
    float4 k0 = ((const float4*)g_k[0])[i];
    float4 ynext = yv, k0next = k0;
    if (acc) {
        float4 y1 = ((const float4*)g_y1)[i];
        float4 k2 = ((const float4*)g_k[2])[i];
        float4 k3 = ((const float4*)g_k[3])[i];
        float4 k4 = ((const float4*)g_k[4])[i];
        float4 k5 = ((const float4*)g_k[5])[i];
        float4 k6 = ((const float4*)g_k[6])[i];
        float4 ym;
        ym.x = yv.x + dt * (CM0*k0.x + CM2*k2.x + CM3*k3.x + CM4*k4.x + CM5*k5.x + CM6*k6.x);
        ym.y = yv.y + dt * (CM0*k0.y + CM2*k2.y + CM3*k3.y + CM4*k4.y + CM5*k5.y + CM6*k6.y);
        ym.z = yv.z + dt * (CM0*k0.z + CM2*k2.z + CM3*k3.z + CM4*k4.z + CM5*k5.z + CM6*k6.z);
        ym.w = yv.w + dt * (CM0*k0.w + CM2*k2.w + CM3*k3.w + CM4*k4.w + CM5*k5.w + CM6*k6.w);
        ((float4*)g_y0s)[i] = yv;
        ((float4*)g_f0s)[i] = k0;
        ((float4*)g_f1s)[i] = k6;
        ((float4*)g_ymid)[i] = ym;
        ((float4*)g_y)[i] = y1;
        ((float4*)g_k[0])[i] = k6;
        ynext = y1; k0next = k6;
    }
    if (!done_new) {
        float4 X;
        X.x = ynext.x + ndt * B21c * k0next.x;
        X.y = ynext.y + ndt * B21c * k0next.y;
        X.z = ynext.z + ndt * B21c * k0next.z;
        X.w = ynext.w + ndt * B21c * k0next.w;
        __nv_bfloat162 h01, h23, l01, l23;
        bf16_split2(X.x, X.y, h01, l01);
        bf16_split2(X.z, X.w, h23, l23);
        ((__nv_bfloat162*)g_Xhi)[2*i]   = h01;
        ((__nv_bfloat162*)g_Xhi)[2*i+1] = h23;
        ((__nv_bfloat162*)g_Xlo)[2*i]   = l01;
        ((__nv_bfloat162*)g_Xlo)[2*i+1] = l23;
    }
}

// ---------------- final quartic interpolation at t=1 ----------------
__global__ void interp_kernel(int p) {
    int i = blockIdx.x * 256 + threadIdx.x;
    const Ctl& ct = g_ctl2[p];
    float t1 = ct.t, t0 = ct.last_t, dts = ct.dt_used;
    float x = (1.0f - t0) / (t1 - t0);
    float4 y0 = ((const float4*)g_y0s)[i];
    float4 y1 = ((const float4*)g_y)[i];
    float4 f0 = ((const float4*)g_f0s)[i];
    float4 f1 = ((const float4*)g_f1s)[i];
    float4 ym = ((const float4*)g_ymid)[i];
    float4 o;
#define INTERPC(c) { \
        float a = 2.f*dts*(f1.c - f0.c) - 8.f*(y1.c + y0.c) + 16.f*ym.c; \
        float b = dts*(5.f*f0.c - 3.f*f1.c) + 18.f*y0.c + 14.f*y1.c - 32.f*ym.c; \
        float cc = dts*(f1.c - 4.f*f0.c) - 11.f*y0.c - 5.f*y1.c + 16.f*ym.c; \
        float d = dts*f0.c; \
        float e = y0.c; \
        o.c = (((a*x + b)*x + cc)*x + d)*x + e; }
    INTERPC(x) INTERPC(y) INTERPC(z) INTERPC(w)
#undef INTERPC
    ((float4*)g_yout)[i] = o;
}

__global__ void gather_kernel(const int* __restrict__ indices, float* __restrict__ out) {
    int i = blockIdx.x * 256 + threadIdx.x;
    if (i < B_ * K_) {
        int b = i / K_;
        out[i] = g_yout[(size_t)b * D_ + indices[i]];
    }
}

// ---------------- orchestration ----------------
extern "C" void kernel_launch(void* const* d_in, const int* in_sizes, int n_in,
                              void* d_out, int out_size)
{
    const float* x  = (const float*)d_in[0];
    const float* W1 = (const float*)d_in[1];
    const float* b1 = (const float*)d_in[2];
    const float* W2 = (const float*)d_in[3];
    const float* b2 = (const float*)d_in[4];
    const int*  idx = (const int*)d_in[5];
    float* out = (float*)d_out;

    cudaFuncSetAttribute(gemm1_kernel, cudaFuncAttributeMaxDynamicSharedMemorySize, G1_SMEM);
    cudaFuncSetAttribute(gemm2_kernel, cudaFuncAttributeMaxDynamicSharedMemorySize, G2_SMEM);

    float *k[7];
    Ctl* ctl2;
    cudaGetSymbolAddress((void**)&ctl2, g_ctl2);
    {
        float* kbase;
        cudaGetSymbolAddress((void**)&kbase, g_k);
        for (int j = 0; j < 7; j++) k[j] = kbase + (size_t)j * ND;
    }
    const float* dt_ptr = &ctl2[0].dt;
    const float* h0_ptr = &ctl2[0].h0;

    dim3 gg1(8, 64), gg2(2, 64), blk2(512);
    dim3 ge(NV / 256), be(256);

    // tableau
    const float B21 = (float)(1.0/5.0);
    const float B31 = (float)(3.0/40.0),   B32 = (float)(9.0/40.0);
    const float B41 = (float)(44.0/45.0),  B42 = (float)(-56.0/15.0),  B43 = (float)(32.0/9.0);
    const float B51 = (float)(19372.0/6561.0), B52 = (float)(-25360.0/2187.0),
                B53 = (float)(64448.0/6561.0), B54 = (float)(-212.0/729.0);
    const float B61 = (float)(9017.0/3168.0),  B62 = (float)(-355.0/33.0),
                B63 = (float)(46732.0/5247.0), B64 = (float)(49.0/176.0),
                B65 = (float)(-5103.0/18656.0);
    const float CS0 = (float)(35.0/384.0), CS2 = (float)(500.0/1113.0),
                CS3 = (float)(125.0/192.0), CS4 = (float)(-2187.0/6784.0),
                CS5 = (float)(11.0/84.0);

    // init
    prep_w1_kernel<<<1024, 256>>>(W1);     // also inits ctl
    prep_w2_kernel<<<1024, 256>>>(W2);
    copysplit_kernel<<<ge, be>>>((const float4*)x);
    gemm1_kernel<<<gg1, blk2, G1_SMEM>>>(0, b1);
    gemm2_kernel<<<gg2, blk2, G2_SMEM>>>(0, b2, k[0], 0, 0, 0,0,0,0,0,0, 0.f);
    // initial step size (Hairer)
    red_d01_kernel<<<ge, be>>>();
    fin_d01_kernel<<<1, 256>>>();
    split_combine_kernel<<<ge, be>>>(h0_ptr, 1.f);
    gemm1_kernel<<<gg1, blk2, G1_SMEM>>>(0, b1);
    gemm2_kernel<<<gg2, blk2, G2_SMEM>>>(0, b2, k[1], 0, 0, 0,0,0,0,0,0, 0.f);
    red_d2_kernel<<<ge, be>>>();
    fin_d2_kernel<<<1, 256>>>();
    // X1 = y + dt*B21*k0
    split_combine_kernel<<<ge, be>>>(dt_ptr, B21);

    for (int s = 0; s < NMAX; s++) {
        int p = s & 1;
        gemm1_kernel<<<gg1, blk2, G1_SMEM>>>(p, b1);
        gemm2_kernel<<<gg2, blk2, G2_SMEM>>>(p, b2, k[1], 1, 1, B31,0,0,0,0,0, B32);
        gemm1_kernel<<<gg1, blk2, G1_SMEM>>>(p, b1);
        gemm2_kernel<<<gg2, blk2, G2_SMEM>>>(p, b2, k[2], 1, 2, B41,B42,0,0,0,0, B43);
        gemm1_kernel<<<gg1, blk2, G1_SMEM>>>(p, b1);
        gemm2_kernel<<<gg2, blk2, G2_SMEM>>>(p, b2, k[3], 1, 3, B51,B52,B53,0,0,0, B54);
        gemm1_kernel<<<gg1, blk2, G1_SMEM>>>(p, b1);
        gemm2_kernel<<<gg2, blk2, G2_SMEM>>>(p, b2, k[4], 1, 4, B61,B62,B63,B64,0,0, B65);
        gemm1_kernel<<<gg1, blk2, G1_SMEM>>>(p, b1);
        gemm2_kernel<<<gg2, blk2, G2_SMEM>>>(p, b2, k[5], 3, 5, CS0,0.f,CS2,CS3,CS4,0, CS5);
        gemm1_kernel<<<gg1, blk2, G1_SMEM>>>(p, b1);
        gemm2_kernel<<<gg2, blk2, G2_SMEM>>>(p, b2, k[6], 2, 6, CE0,0.f,CE2,CE3,CE4,CE5, CE6);
        applyctl_kernel<<<ge, be>>>(p, B21);
    }

    interp_kernel<<<ge, be>>>(NMAX & 1);
    {
        int n = B_ * K_;
        gather_kernel<<<(n + 255) / 256, 256>>>(idx, out);
    }
}

// round 15
// speedup vs baseline: 1.0340x; 1.0340x over previous
#include <cuda_runtime.h>
#include <cuda_bf16.h>
#include <cstdint>
#include <math.h>

// dims
#define B_ 4096
#define D_ 256
#define H_ 1024
#define K_ 128
#define ND (B_*D_)
#define NV (ND/4)
#define NMAX 6
#define RTOL 1e-3f
#define ATOL 1e-3f

// dopri5 error coefficients (c_sol - c_bhat)
#define CE0 ((float)(35.0/384.0 - 1951.0/21600.0))
#define CE2 ((float)(500.0/1113.0 - 22642.0/50085.0))
#define CE3 ((float)(125.0/192.0 - 451.0/720.0))
#define CE4 ((float)(-2187.0/6784.0 + 12231.0/42400.0))
#define CE5 ((float)(11.0/84.0 - 649.0/6300.0))
#define CE6 ((float)(-1.0/60.0))
// dopri5 midpoint coefficients (interp fit)
#define CM0 ((float)(6025192743.0/30085553152.0/2.0))
#define CM2 ((float)(51252292925.0/65400821598.0/2.0))
#define CM3 ((float)(-2691868925.0/45128329728.0/2.0))
#define CM4 ((float)(187940372067.0/1594534317056.0/2.0))
#define CM5 ((float)(-1776094331.0/19743644256.0/2.0))
#define CM6 ((float)(11237099.0/235043384.0/2.0))

struct Ctl {
    float t, dt, last_t, dt_used, h0, d1;
    int accept, done;
};
__device__ Ctl g_ctl2[2];
__device__ __align__(16) float g_y[ND];
__device__ __align__(16) float g_y1[ND];
__device__ __align__(16) float g_k[7][ND];
__device__ __align__(16) float g_y0s[ND], g_ymid[ND], g_f0s[ND], g_f1s[ND];
__device__ __align__(16) float g_yout[ND];
__device__ __align__(16) float g_part[2048];
__device__ __align__(16) __nv_bfloat16 g_Xhi[ND], g_Xlo[ND];
__device__ __align__(16) __nv_bfloat16 g_Hhi[B_ * H_], g_Hlo[B_ * H_];
__device__ __align__(16) __nv_bfloat16 g_W1thi[H_ * D_], g_W1tlo[H_ * D_]; // W1^T [H,D]
__device__ __align__(16) __nv_bfloat16 g_W2thi[D_ * H_], g_W2tlo[D_ * H_]; // W2^T [D,H]

#define SWZ128(b) ((b) ^ (((b) >> 3) & 0x70))

__device__ __forceinline__ uint32_t smem_u32(const void* p) {
    uint32_t a;
    asm("{ .reg .u64 t; cvta.to.shared.u64 t, %1; cvt.u32.u64 %0, t; }" : "=r"(a) : "l"(p));
    return a;
}
__device__ __forceinline__ void cp16(uint32_t saddr, const void* gptr) {
    asm volatile("cp.async.cg.shared.global [%0], [%1], 16;" :: "r"(saddr), "l"(gptr));
}
#define CP_COMMIT() asm volatile("cp.async.commit_group;" ::: "memory")
#define CP_WAIT0()  asm volatile("cp.async.wait_group 0;" ::: "memory")
#define CP_WAIT1()  asm volatile("cp.async.wait_group 1;" ::: "memory")
__device__ __forceinline__ void ldsm_x4(uint32_t* r, uint32_t addr) {
    asm volatile("ldmatrix.sync.aligned.m8n8.x4.shared.b16 {%0,%1,%2,%3}, [%4];"
        : "=r"(r[0]), "=r"(r[1]), "=r"(r[2]), "=r"(r[3]) : "r"(addr));
}
__device__ __forceinline__ void mma16816(float* c, const uint32_t* a, const uint32_t* b) {
    asm volatile("mma.sync.aligned.m16n8k16.row.col.f32.bf16.bf16.f32 "
        "{%0,%1,%2,%3}, {%4,%5,%6,%7}, {%8,%9}, {%0,%1,%2,%3};"
        : "+f"(c[0]), "+f"(c[1]), "+f"(c[2]), "+f"(c[3])
        : "r"(a[0]), "r"(a[1]), "r"(a[2]), "r"(a[3]), "r"(b[0]), "r"(b[1]));
}
__device__ __forceinline__ void bf16_split2(float a, float b, __nv_bfloat162& h, __nv_bfloat162& l) {
    h.x = __float2bfloat16(a); h.y = __float2bfloat16(b);
    l.x = __float2bfloat16(a - __bfloat162float(h.x));
    l.y = __float2bfloat16(b - __bfloat162float(h.y));
}

// ================= small kernels =================
// weight prep W1 + ctl init
__global__ void prep_w1_kernel(const float* __restrict__ W1) {
    if (blockIdx.x == 0 && threadIdx.x == 0) {
        for (int j = 0; j < 2; j++) {
            g_ctl2[j].t = 0.f; g_ctl2[j].dt = 0.f; g_ctl2[j].last_t = 0.f;
            g_ctl2[j].dt_used = 0.f; g_ctl2[j].h0 = 0.f; g_ctl2[j].d1 = 0.f;
            g_ctl2[j].accept = 0; g_ctl2[j].done = 0;
        }
    }
    int o = blockIdx.x * 256 + threadIdx.x;
    if (o < H_ * D_) {
        int h = o >> 8, d = o & 255;
        float v = W1[(size_t)d * H_ + h];
        __nv_bfloat16 hi = __float2bfloat16(v);
        g_W1thi[o] = hi;
        g_W1tlo[o] = __float2bfloat16(v - __bfloat162float(hi));
    }
}
// W2 [H,D] -> W2t hi/lo [D,H]
__global__ void prep_w2_kernel(const float* __restrict__ W2) {
    int o = blockIdx.x * 256 + threadIdx.x;
    if (o < D_ * H_) {
        int d = o >> 10, h = o & 1023;
        float v = W2[(size_t)h * D_ + d];
        __nv_bfloat16 hi = __float2bfloat16(v);
        g_W2thi[o] = hi;
        g_W2tlo[o] = __float2bfloat16(v - __bfloat162float(hi));
    }
}

// y = x; X = x (bf16 split)
__global__ void copysplit_kernel(const float4* __restrict__ x) {
    int i = blockIdx.x * 256 + threadIdx.x;
    float4 X = x[i];
    ((float4*)g_y)[i] = X;
    __nv_bfloat162 h01, h23, l01, l23;
    bf16_split2(X.x, X.y, h01, l01);
    bf16_split2(X.z, X.w, h23, l23);
    ((__nv_bfloat162*)g_Xhi)[2*i]   = h01;
    ((__nv_bfloat162*)g_Xhi)[2*i+1] = h23;
    ((__nv_bfloat162*)g_Xlo)[2*i]   = l01;
    ((__nv_bfloat162*)g_Xlo)[2*i+1] = l23;
}

// init-phase combine + split: X = y + (*scal)*c0*k0
__global__ void split_combine_kernel(const float* __restrict__ scal, float c0)
{
    int i = blockIdx.x * 256 + threadIdx.x;
    float dt = *scal;
    float4 kv = ((const float4*)g_k[0])[i];
    float4 yv = ((const float4*)g_y)[i];
    float4 X = make_float4(yv.x + dt * c0 * kv.x, yv.y + dt * c0 * kv.y,
                           yv.z + dt * c0 * kv.z, yv.w + dt * c0 * kv.w);
    __nv_bfloat162 h01, h23, l01, l23;
    bf16_split2(X.x, X.y, h01, l01);
    bf16_split2(X.z, X.w, h23, l23);
    ((__nv_bfloat162*)g_Xhi)[2*i]   = h01;
    ((__nv_bfloat162*)g_Xhi)[2*i+1] = h23;
    ((__nv_bfloat162*)g_Xlo)[2*i]   = l01;
    ((__nv_bfloat162*)g_Xlo)[2*i+1] = l23;
}

// ================= GEMM1: H = tanh(X @ W1 + b1) =================
// tile 64x128, K=256 (4 chunks of 64), cp.async 2-stage, occupancy 2. grid (8, 64).
// 256 threads, 8 warps (2m x 4n, warp 32x32). Paired-x4 B fragments.
#define G1_STAGE 49152
#define G1_SMEM  (2 * G1_STAGE)

__global__ void __launch_bounds__(256, 2) gemm1_kernel(int p, const float* __restrict__ bias)
{
    if (g_ctl2[p].done) return;
    extern __shared__ char smem[];
    const uint32_t smb = smem_u32(smem);

    const int tid = threadIdx.x;
    const int w = tid >> 5, l = tid & 31;
    const int wm = w >> 2, wn = w & 3;
    const int m0 = blockIdx.y * 64;
    const int n0 = blockIdx.x * 128;

    float acc[2][4][4];
#pragma unroll
    for (int mf = 0; mf < 2; mf++)
#pragma unroll
        for (int nf = 0; nf < 4; nf++)
#pragma unroll
            for (int e = 0; e < 4; e++) acc[mf][nf][e] = 0.f;

    const int rowA = wm * 32 + (l & 15);
    const int colA = (l >> 4) * 8;
    // B x4 lane mapping: two n8k16 frags per ldmatrix
    const int rowB4 = wn * 32 + ((l >> 4) * 8) + (l & 7);
    const int colB4 = ((l >> 3) & 1) * 8;

    auto load_chunk = [&](int c, int b) {
        const uint32_t base = smb + b * G1_STAGE;
        const int kc = c * 64;
#pragma unroll
        for (int i = 0; i < 2; i++) {
            int t = tid + i * 256;
            int r = t >> 3, g = t & 7;
            size_t src = (size_t)(m0 + r) * D_ + kc + g * 8;
            uint32_t sw = SWZ128(r * 128 + g * 16);
            cp16(base + sw,         g_Xhi + src);
            cp16(base + 8192 + sw,  g_Xlo + src);
        }
#pragma unroll
        for (int i = 0; i < 4; i++) {
            int t = tid + i * 256;
            int r = t >> 3, g = t & 7;
            size_t src = (size_t)(n0 + r) * D_ + kc + g * 8;
            uint32_t sw = SWZ128(r * 128 + g * 16);
            cp16(base + 16384 + sw, g_W1thi + src);
            cp16(base + 32768 + sw, g_W1tlo + src);
        }
    };

    load_chunk(0, 0);
    CP_COMMIT();

    for (int c = 0; c < 4; c++) {
        if (c + 1 < 4) {
            load_chunk(c + 1, (c + 1) & 1);
            CP_COMMIT();
            CP_WAIT1();
        } else {
            CP_WAIT0();
        }
        __syncthreads();

        const uint32_t base = smb + (c & 1) * G1_STAGE;
        const uint32_t sAh = base, sAl = base + 8192;
        const uint32_t sBh = base + 16384, sBl = base + 32768;
#pragma unroll
        for (int kf = 0; kf < 4; kf++) {
            uint32_t ah[2][4], al[2][4], bh4[2][4], bl4[2][4];
#pragma unroll
            for (int mf = 0; mf < 2; mf++) {
                uint32_t off = SWZ128((rowA + mf * 16) * 128 + (kf * 16 + colA) * 2);
                ldsm_x4(ah[mf], sAh + off);
                ldsm_x4(al[mf], sAl + off);
            }
#pragma unroll
            for (int pb = 0; pb < 2; pb++) {
                uint32_t off = SWZ128((rowB4 + pb * 16) * 128 + (kf * 16 + colB4) * 2);
                ldsm_x4(bh4[pb], sBh + off);
                ldsm_x4(bl4[pb], sBl + off);
            }
            // frag nf: pb = nf>>1, half = nf&1 -> regs {r[half*2], r[half*2+1]}
#pragma unroll
            for (int mf = 0; mf < 2; mf++)
#pragma unroll
                for (int nf = 0; nf < 4; nf++) {
                    const uint32_t* bhf = &bh4[nf >> 1][(nf & 1) * 2];
                    const uint32_t* blf = &bl4[nf >> 1][(nf & 1) * 2];
                    mma16816(acc[mf][nf], ah[mf], bhf);
                    mma16816(acc[mf][nf], ah[mf], blf);
                    mma16816(acc[mf][nf], al[mf], bhf);
                }
        }
        __syncthreads();
    }

    const int rr = l >> 2;
    const int cc2 = (l & 3) * 2;
#pragma unroll
    for (int mf = 0; mf < 2; mf++) {
#pragma unroll
        for (int nf = 0; nf < 4; nf++) {
            int r0 = m0 + wm * 32 + mf * 16 + rr;
            int ci = n0 + wn * 32 + nf * 8 + cc2;
            float2 bb = *(const float2*)&bias[ci];
#pragma unroll
            for (int hh = 0; hh < 2; hh++) {
                int r = r0 + hh * 8;
                float v0 = tanhf(acc[mf][nf][hh * 2 + 0] + bb.x);
                float v1 = tanhf(acc[mf][nf][hh * 2 + 1] + bb.y);
                __nv_bfloat162 h, lo2;
                bf16_split2(v0, v1, h, lo2);
                *(__nv_bfloat162*)&g_Hhi[(size_t)r * H_ + ci] = h;
                *(__nv_bfloat162*)&g_Hlo[(size_t)r * H_ + ci] = lo2;
            }
        }
    }
}

// ================= GEMM2: k = H @ W2 + b2, epilogue-fused =================
// tile 64x128, K=1024 (16 chunks), 512 threads (16 warps, 4m x 4n, warp 16x32),
// 3-stage cp.async single-sync mainloop. grid (2, 64) = 128 CTAs (1/SM).
#define G2_STAGE 49152
#define G2_SMEM  (3 * G2_STAGE)

__global__ void __launch_bounds__(512, 1) gemm2_kernel(
    int p, const float* __restrict__ b2, float* __restrict__ kout,
    int mode, int ngm,
    float cg0, float cg1, float cg2, float cg3, float cg4, float cg5, float cl)
{
    const Ctl& ct = g_ctl2[p];
    if (ct.done) return;
    extern __shared__ char smem[];
    const uint32_t smb = smem_u32(smem);

    const int tid = threadIdx.x;
    const int w = tid >> 5, l = tid & 31;
    const int wm = w >> 2, wn = w & 3;
    const int m0 = blockIdx.y * 64;
    const int n0 = blockIdx.x * 128;
    float cg[6] = {cg0, cg1, cg2, cg3, cg4, cg5};

    float acc[4][4];
#pragma unroll
    for (int nf = 0; nf < 4; nf++)
#pragma unroll
        for (int e = 0; e < 4; e++) acc[nf][e] = 0.f;

    const int rowA = wm * 16 + (l & 15);
    const int colA = (l >> 4) * 8;
    const int rowB4 = wn * 32 + ((l >> 4) * 8) + (l & 7);
    const int colB4 = ((l >> 3) & 1) * 8;

    auto load_chunk = [&](int c, int b) {
        const uint32_t base = smb + b * G2_STAGE;
        const int kc = c * 64;
        {
            int r = tid >> 3, g = tid & 7;
            size_t src = (size_t)(m0 + r) * H_ + kc + g * 8;
            uint32_t sw = SWZ128(r * 128 + g * 16);
            cp16(base + sw,         g_Hhi + src);
            cp16(base + 8192 + sw,  g_Hlo + src);
        }
#pragma unroll
        for (int i = 0; i < 2; i++) {
            int t = tid + i * 512;
            int r = t >> 3, g = t & 7;
            size_t src = (size_t)(n0 + r) * H_ + kc + g * 8;
            uint32_t sw = SWZ128(r * 128 + g * 16);
            cp16(base + 16384 + sw, g_W2thi + src);
            cp16(base + 32768 + sw, g_W2tlo + src);
        }
    };

    load_chunk(0, 0); CP_COMMIT();
    load_chunk(1, 1); CP_COMMIT();

    for (int c = 0; c < 16; c++) {
        if (c < 15) CP_WAIT1(); else CP_WAIT0();
        __syncthreads();
        if (c + 2 < 16) { load_chunk(c + 2, (c + 2) % 3); CP_COMMIT(); }

        const uint32_t base = smb + (c % 3) * G2_STAGE;
        const uint32_t sAh = base, sAl = base + 8192;
        const uint32_t sBh = base + 16384, sBl = base + 32768;
#pragma unroll
        for (int kf = 0; kf < 4; kf++) {
            uint32_t ah[4], al[4], bh4[2][4], bl4[2][4];
            {
                uint32_t off = SWZ128(rowA * 128 + (kf * 16 + colA) * 2);
                ldsm_x4(ah, sAh + off);
                ldsm_x4(al, sAl + off);
            }
#pragma unroll
            for (int pb = 0; pb < 2; pb++) {
                uint32_t off = SWZ128((rowB4 + pb * 16) * 128 + (kf * 16 + colB4) * 2);
                ldsm_x4(bh4[pb], sBh + off);
                ldsm_x4(bl4[pb], sBl + off);
            }
#pragma unroll
            for (int nf = 0; nf < 4; nf++) {
                const uint32_t* bhf = &bh4[nf >> 1][(nf & 1) * 2];
                const uint32_t* blf = &bl4[nf >> 1][(nf & 1) * 2];
                mma16816(acc[nf], ah, bhf);
                mma16816(acc[nf], ah, blf);
                mma16816(acc[nf], al, bhf);
            }
        }
    }

    // epilogue
    const int rr = l >> 2;
    const int cc2 = (l & 3) * 2;
    const float dt = ct.dt;
    float errsum = 0.f;
#pragma unroll
    for (int nf = 0; nf < 4; nf++) {
        int r0 = m0 + wm * 16 + rr;
        int ci = n0 + wn * 32 + nf * 8 + cc2;
        float2 bb = *(const float2*)&b2[ci];
#pragma unroll
        for (int hh = 0; hh < 2; hh++) {
            int r = r0 + hh * 8;
            float v0 = acc[nf][hh * 2 + 0] + bb.x;
            float v1 = acc[nf][hh * 2 + 1] + bb.y;
            size_t off = (size_t)r * D_ + ci;
            *(float2*)&kout[off] = make_float2(v0, v1);
            if (mode == 1 || mode == 3) {
                float2 yv = *(const float2*)&g_y[off];
                float sx = cl * v0, sy = cl * v1;
                for (int j = 0; j < ngm; j++) {
                    if (cg[j] != 0.f) {
                        float2 kj = *(const float2*)&g_k[j][off];
                        sx += cg[j] * kj.x; sy += cg[j] * kj.y;
                    }
                }
                float X0 = yv.x + dt * sx, X1 = yv.y + dt * sy;
                if (mode == 3) *(float2*)&g_y1[off] = make_float2(X0, X1);
                __nv_bfloat162 h, lo2;
                bf16_split2(X0, X1, h, lo2);
                *(__nv_bfloat162*)&g_Xhi[off] = h;
                *(__nv_bfloat162*)&g_Xlo[off] = lo2;
            } else if (mode == 2) {
                float2 yv  = *(const float2*)&g_y[off];
                float2 y1v = *(const float2*)&g_y1[off];
                float sx = cl * v0, sy = cl * v1;
                for (int j = 0; j < ngm; j++) {
                    if (cg[j] != 0.f) {
                        float2 kj = *(const float2*)&g_k[j][off];
                        sx += cg[j] * kj.x; sy += cg[j] * kj.y;
                    }
                }
                float e0 = dt * sx, e1 = dt * sy;
                float t0 = ATOL + RTOL * fmaxf(fabsf(yv.x), fabsf(y1v.x));
                float t1 = ATOL + RTOL * fmaxf(fabsf(yv.y), fabsf(y1v.y));
                float r0f = e0 / t0, r1f = e1 / t1;
                errsum += r0f * r0f + r1f * r1f;
            }
        }
    }
    if (mode == 2) {
        float* sred = (float*)smem;
        __syncthreads();
        sred[tid] = errsum;
        __syncthreads();
        for (int o = 256; o > 0; o >>= 1) {
            if (tid < o) sred[tid] += sred[tid + o];
            __syncthreads();
        }
        if (tid == 0) g_part[blockIdx.y * gridDim.x + blockIdx.x] = sred[0];
    }
}

// ---------------- init-step-size reductions (ctl2[0]) ----------------
__global__ void red_d01_kernel() {
    int i = blockIdx.x * 256 + threadIdx.x;
    float4 yv = ((const float4*)g_y)[i];
    float4 fv = ((const float4*)g_k[0])[i];
    float s0 = 0.f, s1 = 0.f;
    {
        float sc, a, b;
        sc = ATOL + fabsf(yv.x) * RTOL; a = yv.x / sc; b = fv.x / sc; s0 += a*a; s1 += b*b;
        sc = ATOL + fabsf(yv.y) * RTOL; a = yv.y / sc; b = fv.y / sc; s0 += a*a; s1 += b*b;
        sc = ATOL + fabsf(yv.z) * RTOL; a = yv.z / sc; b = fv.z / sc; s0 += a*a; s1 += b*b;
        sc = ATOL + fabsf(yv.w) * RTOL; a = yv.w / sc; b = fv.w / sc; s0 += a*a; s1 += b*b;
    }
    __shared__ float sm0[256], sm1[256];
    sm0[threadIdx.x] = s0; sm1[threadIdx.x] = s1;
    __syncthreads();
    for (int off = 128; off > 0; off >>= 1) {
        if (threadIdx.x < off) {
            sm0[threadIdx.x] += sm0[threadIdx.x + off];
            sm1[threadIdx.x] += sm1[threadIdx.x + off];
        }
        __syncthreads();
    }
    if (threadIdx.x == 0) { g_part[blockIdx.x] = sm0[0]; g_part[1024 + blockIdx.x] = sm1[0]; }
}

__global__ void fin_d01_kernel() {
    __shared__ float sm0[256], sm1[256];
    float s0 = 0.f, s1 = 0.f;
    for (int j = threadIdx.x; j < 1024; j += 256) { s0 += g_part[j]; s1 += g_part[1024 + j]; }
    sm0[threadIdx.x] = s0; sm1[threadIdx.x] = s1;
    __syncthreads();
    for (int off = 128; off > 0; off >>= 1) {
        if (threadIdx.x < off) {
            sm0[threadIdx.x] += sm0[threadIdx.x + off];
            sm1[threadIdx.x] += sm1[threadIdx.x + off];
        }
        __syncthreads();
    }
    if (threadIdx.x == 0) {
        float d0 = sqrtf(sm0[0]);
        float d1 = sqrtf(sm1[0]);
        float h0 = (d0 < 1e-5f || d1 < 1e-5f) ? 1e-6f : 0.01f * d0 / d1;
        g_ctl2[0].h0 = h0;
        g_ctl2[0].d1 = d1;
    }
}

__global__ void red_d2_kernel() {
    int i = blockIdx.x * 256 + threadIdx.x;
    float4 yv = ((const float4*)g_y)[i];
    float4 f0 = ((const float4*)g_k[0])[i];
    float4 f1 = ((const float4*)g_k[1])[i];
    float s = 0.f;
    {
        float sc, a;
        sc = ATOL + fabsf(yv.x) * RTOL; a = (f1.x - f0.x) / sc; s += a*a;
        sc = ATOL + fabsf(yv.y) * RTOL; a = (f1.y - f0.y) / sc; s += a*a;
        sc = ATOL + fabsf(yv.z) * RTOL; a = (f1.z - f0.z) / sc; s += a*a;
        sc = ATOL + fabsf(yv.w) * RTOL; a = (f1.w - f0.w) / sc; s += a*a;
    }
    __shared__ float sm[256];
    sm[threadIdx.x] = s;
    __syncthreads();
    for (int off = 128; off > 0; off >>= 1) {
        if (threadIdx.x < off) sm[threadIdx.x] += sm[threadIdx.x + off];
        __syncthreads();
    }
    if (threadIdx.x == 0) g_part[blockIdx.x] = sm[0];
}

__global__ void fin_d2_kernel() {
    __shared__ float sm[256];
    float s = 0.f;
    for (int j = threadIdx.x; j < 1024; j += 256) s += g_part[j];
    sm[threadIdx.x] = s;
    __syncthreads();
    for (int off = 128; off > 0; off >>= 1) {
        if (threadIdx.x < off) sm[threadIdx.x] += sm[threadIdx.x + off];
        __syncthreads();
    }
    if (threadIdx.x == 0) {
        float d2 = sqrtf(sm[0]) / g_ctl2[0].h0;
        float d1 = g_ctl2[0].d1;
        float h1;
        if (d1 <= 1e-15f && d2 <= 1e-15f)
            h1 = fmaxf(1e-6f, g_ctl2[0].h0 * 1e-3f);
        else
            h1 = powf(0.01f / fmaxf(d1, d2), 0.2f);
        float dt = fminf(100.f * g_ctl2[0].h0, h1);
        g_ctl2[0].dt = dt;
        g_ctl2[0].t = 0.f; g_ctl2[0].last_t = 0.f;
        g_ctl2[0].done = 0; g_ctl2[0].accept = 0;
    }
}

// ---------------- fused controller + apply + next-stage-1 combine ----------------
__global__ void applyctl_kernel(int p, float B21c) {
    const Ctl ci = g_ctl2[p];
    Ctl* co = &g_ctl2[1 - p];
    if (ci.done) {
        if (blockIdx.x == 0 && threadIdx.x == 0) *co = ci;
        return;
    }
    __shared__ float sm[128];
    if (threadIdx.x < 128) sm[threadIdx.x] = g_part[threadIdx.x];
    __syncthreads();
    for (int o = 64; o > 0; o >>= 1) {
        if (threadIdx.x < o) sm[threadIdx.x] += sm[threadIdx.x + o];
        __syncthreads();
    }
    float total = sm[0];

    float ratio = sqrtf(total / (float)ND);
    float t = ci.t, dt = ci.dt;
    float next_t = t + dt;
    int acc = (ratio <= 1.0f);
    float fac;
    if (ratio == 0.f) {
        fac = 10.f;
    } else {
        float r = fmaxf(ratio, 0.f);
        float dfac = (r < 1.f) ? 1.f : 0.2f;
        fac = fminf(10.f, fmaxf(0.9f * powf(r, -0.2f), dfac));
    }
    float ndt = fmaxf(dt * fac, 0.f);
    int done_new = (acc && next_t >= 1.0f) ? 1 : 0;

    if (blockIdx.x == 0 && threadIdx.x == 0) {
        co->t = acc ? next_t : t;
        co->dt = ndt;
        co->last_t = acc ? t : ci.last_t;
        co->dt_used = dt;
        co->h0 = ci.h0; co->d1 = ci.d1;
        co->accept = acc;
        co->done = done_new;
    }

    int i = blockIdx.x * 256 + threadIdx.x;
    float4 yv = ((const float4*)g_y)[i];
    float4 k0 = ((const float4*)g_k[0])[i];
    float4 ynext = yv, k0next = k0;
    if (acc) {
        float4 y1 = ((const float4*)g_y1)[i];
        float4 k2 = ((const float4*)g_k[2])[i];
        float4 k3 = ((const float4*)g_k[3])[i];
        float4 k4 = ((const float4*)g_k[4])[i];
        float4 k5 = ((const float4*)g_k[5])[i];
        float4 k6 = ((const float4*)g_k[6])[i];
        float4 ym;
        ym.x = yv.x + dt * (CM0*k0.x + CM2*k2.x + CM3*k3.x + CM4*k4.x + CM5*k5.x + CM6*k6.x);
        ym.y = yv.y + dt * (CM0*k0.y + CM2*k2.y + CM3*k3.y + CM4*k4.y + CM5*k5.y + CM6*k6.y);
        ym.z = yv.z + dt * (CM0*k0.z + CM2*k2.z + CM3*k3.z + CM4*k4.z + CM5*k5.z + CM6*k6.z);
        ym.w = yv.w + dt * (CM0*k0.w + CM2*k2.w + CM3*k3.w + CM4*k4.w + CM5*k5.w + CM6*k6.w);
        ((float4*)g_y0s)[i] = yv;
        ((float4*)g_f0s)[i] = k0;
        ((float4*)g_f1s)[i] = k6;
        ((float4*)g_ymid)[i] = ym;
        ((float4*)g_y)[i] = y1;
        ((float4*)g_k[0])[i] = k6;
        ynext = y1; k0next = k6;
    }
    if (!done_new) {
        float4 X;
        X.x = ynext.x + ndt * B21c * k0next.x;
        X.y = ynext.y + ndt * B21c * k0next.y;
        X.z = ynext.z + ndt * B21c * k0next.z;
        X.w = ynext.w + ndt * B21c * k0next.w;
        __nv_bfloat162 h01, h23, l01, l23;
        bf16_split2(X.x, X.y, h01, l01);
        bf16_split2(X.z, X.w, h23, l23);
        ((__nv_bfloat162*)g_Xhi)[2*i]   = h01;
        ((__nv_bfloat162*)g_Xhi)[2*i+1] = h23;
        ((__nv_bfloat162*)g_Xlo)[2*i]   = l01;
        ((__nv_bfloat162*)g_Xlo)[2*i+1] = l23;
    }
}

// ---------------- final quartic interpolation at t=1 ----------------
__global__ void interp_kernel(int p) {
    int i = blockIdx.x * 256 + threadIdx.x;
    const Ctl& ct = g_ctl2[p];
    float t1 = ct.t, t0 = ct.last_t, dts = ct.dt_used;
    float x = (1.0f - t0) / (t1 - t0);
    float4 y0 = ((const float4*)g_y0s)[i];
    float4 y1 = ((const float4*)g_y)[i];
    float4 f0 = ((const float4*)g_f0s)[i];
    float4 f1 = ((const float4*)g_f1s)[i];
    float4 ym = ((const float4*)g_ymid)[i];
    float4 o;
#define INTERPC(c) { \
        float a = 2.f*dts*(f1.c - f0.c) - 8.f*(y1.c + y0.c) + 16.f*ym.c; \
        float b = dts*(5.f*f0.c - 3.f*f1.c) + 18.f*y0.c + 14.f*y1.c - 32.f*ym.c; \
        float cc = dts*(f1.c - 4.f*f0.c) - 11.f*y0.c - 5.f*y1.c + 16.f*ym.c; \
        float d = dts*f0.c; \
        float e = y0.c; \
        o.c = (((a*x + b)*x + cc)*x + d)*x + e; }
    INTERPC(x) INTERPC(y) INTERPC(z) INTERPC(w)
#undef INTERPC
    ((float4*)g_yout)[i] = o;
}

__global__ void gather_kernel(const int* __restrict__ indices, float* __restrict__ out) {
    int i = blockIdx.x * 256 + threadIdx.x;
    if (i < B_ * K_) {
        int b = i / K_;
        out[i] = g_yout[(size_t)b * D_ + indices[i]];
    }
}

// ---------------- orchestration ----------------
extern "C" void kernel_launch(void* const* d_in, const int* in_sizes, int n_in,
                              void* d_out, int out_size)
{
    const float* x  = (const float*)d_in[0];
    const float* W1 = (const float*)d_in[1];
    const float* b1 = (const float*)d_in[2];
    const float* W2 = (const float*)d_in[3];
    const float* b2 = (const float*)d_in[4];
    const int*  idx = (const int*)d_in[5];
    float* out = (float*)d_out;

    cudaFuncSetAttribute(gemm1_kernel, cudaFuncAttributeMaxDynamicSharedMemorySize, G1_SMEM);
    cudaFuncSetAttribute(gemm2_kernel, cudaFuncAttributeMaxDynamicSharedMemorySize, G2_SMEM);

    float *k[7];
    Ctl* ctl2;
    cudaGetSymbolAddress((void**)&ctl2, g_ctl2);
    {
        float* kbase;
        cudaGetSymbolAddress((void**)&kbase, g_k);
        for (int j = 0; j < 7; j++) k[j] = kbase + (size_t)j * ND;
    }
    const float* dt_ptr = &ctl2[0].dt;
    const float* h0_ptr = &ctl2[0].h0;

    dim3 gg1(8, 64), gg2(2, 64), blk(256), blk2(512);
    dim3 ge(NV / 256), be(256);

    // tableau
    const float B21 = (float)(1.0/5.0);
    const float B31 = (float)(3.0/40.0),   B32 = (float)(9.0/40.0);
    const float B41 = (float)(44.0/45.0),  B42 = (float)(-56.0/15.0),  B43 = (float)(32.0/9.0);
    const float B51 = (float)(19372.0/6561.0), B52 = (float)(-25360.0/2187.0),
                B53 = (float)(64448.0/6561.0), B54 = (float)(-212.0/729.0);
    const float B61 = (float)(9017.0/3168.0),  B62 = (float)(-355.0/33.0),
                B63 = (float)(46732.0/5247.0), B64 = (float)(49.0/176.0),
                B65 = (float)(-5103.0/18656.0);
    const float CS0 = (float)(35.0/384.0), CS2 = (float)(500.0/1113.0),
                CS3 = (float)(125.0/192.0), CS4 = (float)(-2187.0/6784.0),
                CS5 = (float)(11.0/84.0);

    // init
    prep_w1_kernel<<<1024, 256>>>(W1);     // also inits ctl
    prep_w2_kernel<<<1024, 256>>>(W2);
    copysplit_kernel<<<ge, be>>>((const float4*)x);
    gemm1_kernel<<<gg1, blk, G1_SMEM>>>(0, b1);
    gemm2_kernel<<<gg2, blk2, G2_SMEM>>>(0, b2, k[0], 0, 0, 0,0,0,0,0,0, 0.f);
    // initial step size (Hairer)
    red_d01_kernel<<<ge, be>>>();
    fin_d01_kernel<<<1, 256>>>();
    split_combine_kernel<<<ge, be>>>(h0_ptr, 1.f);
    gemm1_kernel<<<gg1, blk, G1_SMEM>>>(0, b1);
    gemm2_kernel<<<gg2, blk2, G2_SMEM>>>(0, b2, k[1], 0, 0, 0,0,0,0,0,0, 0.f);
    red_d2_kernel<<<ge, be>>>();
    fin_d2_kernel<<<1, 256>>>();
    // X1 = y + dt*B21*k0
    split_combine_kernel<<<ge, be>>>(dt_ptr, B21);

    for (int s = 0; s < NMAX; s++) {
        int p = s & 1;
        gemm1_kernel<<<gg1, blk, G1_SMEM>>>(p, b1);
        gemm2_kernel<<<gg2, blk2, G2_SMEM>>>(p, b2, k[1], 1, 1, B31,0,0,0,0,0, B32);
        gemm1_kernel<<<gg1, blk, G1_SMEM>>>(p, b1);
        gemm2_kernel<<<gg2, blk2, G2_SMEM>>>(p, b2, k[2], 1, 2, B41,B42,0,0,0,0, B43);
        gemm1_kernel<<<gg1, blk, G1_SMEM>>>(p, b1);
        gemm2_kernel<<<gg2, blk2, G2_SMEM>>>(p, b2, k[3], 1, 3, B51,B52,B53,0,0,0, B54);
        gemm1_kernel<<<gg1, blk, G1_SMEM>>>(p, b1);
        gemm2_kernel<<<gg2, blk2, G2_SMEM>>>(p, b2, k[4], 1, 4, B61,B62,B63,B64,0,0, B65);
        gemm1_kernel<<<gg1, blk, G1_SMEM>>>(p, b1);
        gemm2_kernel<<<gg2, blk2, G2_SMEM>>>(p, b2, k[5], 3, 5, CS0,0.f,CS2,CS3,CS4,0, CS5);
        gemm1_kernel<<<gg1, blk, G1_SMEM>>>(p, b1);
        gemm2_kernel<<<gg2, blk2, G2_SMEM>>>(p, b2, k[6], 2, 6, CE0,0.f,CE2,CE3,CE4,CE5, CE6);
        applyctl_kernel<<<ge, be>>>(p, B21);
    }

    interp_kernel<<<ge, be>>>(NMAX & 1);
    {
        int n = B_ * K_;
        gather_kernel<<<(n + 255) / 256, 256>>>(idx, out);
    }
}